// round 9
// baseline (speedup 1.0000x reference)
#include <cuda_runtime.h>
#include <math.h>
#include <stdint.h>
#include <stddef.h>

#define BB 4
#define SQ 1024
#define EM 256
#define NH 8
#define HD 32
#define MROWS (BB*SQ)          // 4096
#define HID 128                // MLP hidden

// ---------------- scratch (static device globals; allocation-free) ----------
__device__ float g_q[BB*NH*SQ*HD];                 // (b,h,s,d) 4 MB
__device__ float g_k[BB*NH*SQ*HD];
__device__ float g_v[BB*NH*SQ*HD];
__device__ float g_hidden[MROWS*HID];              // 2 MB
__device__ float g_off[MROWS*NH*2];                // (b*S+s)*16 + h*2 + {x,y}
__device__ float g_scores[(size_t)BB*NH*SQ*SQ];    // 128 MB
__device__ float g_att[MROWS*EM];                  // (b,s, h*32+d) 4 MB

// ---------------- QKV: one launch, z picks projection ------------------------
__global__ __launch_bounds__(256) void qkv_kernel(const float* __restrict__ A,
                                                  const float* __restrict__ Wq,
                                                  const float* __restrict__ Wk,
                                                  const float* __restrict__ Wv) {
    __shared__ float As[64][16];
    __shared__ float Bs[16][64];
    const float* W = (blockIdx.z == 0) ? Wq : (blockIdx.z == 1) ? Wk : Wv;
    float* scat    = (blockIdx.z == 0) ? g_q : (blockIdx.z == 1) ? g_k : g_v;
    int tm = blockIdx.x * 64;
    int tn = blockIdx.y * 64;
    int tid = threadIdx.x;
    int tx = tid & 15, ty = tid >> 4;
    float acc[4][4] = {};
    for (int k0 = 0; k0 < EM; k0 += 16) {
        int m  = tid >> 2;
        int kb = (tid & 3) * 4;
        *(float4*)&As[m][kb] = *(const float4*)&A[(size_t)(tm + m) * EM + k0 + kb];
        int kk = tid >> 4;
        int nb = (tid & 15) * 4;
        *(float4*)&Bs[kk][nb] = *(const float4*)&W[(size_t)(k0 + kk) * EM + tn + nb];
        __syncthreads();
#pragma unroll
        for (int k = 0; k < 16; k++) {
            float a[4], bv[4];
#pragma unroll
            for (int i = 0; i < 4; i++) a[i] = As[ty * 4 + i][k];
#pragma unroll
            for (int j = 0; j < 4; j++) bv[j] = Bs[k][tx * 4 + j];
#pragma unroll
            for (int i = 0; i < 4; i++)
#pragma unroll
                for (int j = 0; j < 4; j++) acc[i][j] += a[i] * bv[j];
        }
        __syncthreads();
    }
#pragma unroll
    for (int i = 0; i < 4; i++) {
#pragma unroll
        for (int j = 0; j < 4; j++) {
            int m = tm + ty * 4 + i;
            int n = tn + tx * 4 + j;
            int b = m >> 10, s = m & 1023, h = n >> 5, d = n & 31;
            scat[(((size_t)(b * NH + h)) * SQ + s) * HD + d] = acc[i][j];
        }
    }
}

// ---------------- generic 64x64 GEMM (hidden-GELU / out-proj) ----------------
// mode 3: out = gelu(x@W + bias) -> g_hidden   (N=128)
// mode 4: out = g_att@W + bias -> outp         (N=256)
__global__ __launch_bounds__(256) void gemm64_kernel(const float* __restrict__ A,
                              const float* __restrict__ W,
                              const float* __restrict__ bias,
                              float* __restrict__ outp,
                              int N, int mode) {
    __shared__ float As[64][16];
    __shared__ float Bs[16][64];
    const float* Ap = (mode == 4) ? g_att : A;
    int tm = blockIdx.x * 64;
    int tn = blockIdx.y * 64;
    int tid = threadIdx.x;
    int tx = tid & 15, ty = tid >> 4;
    float acc[4][4] = {};
    for (int k0 = 0; k0 < EM; k0 += 16) {
        int m  = tid >> 2;
        int kb = (tid & 3) * 4;
        *(float4*)&As[m][kb] = *(const float4*)&Ap[(size_t)(tm + m) * EM + k0 + kb];
        int kk = tid >> 4;
        int nb = (tid & 15) * 4;
        *(float4*)&Bs[kk][nb] = *(const float4*)&W[(size_t)(k0 + kk) * N + tn + nb];
        __syncthreads();
#pragma unroll
        for (int k = 0; k < 16; k++) {
            float a[4], bv[4];
#pragma unroll
            for (int i = 0; i < 4; i++) a[i] = As[ty * 4 + i][k];
#pragma unroll
            for (int j = 0; j < 4; j++) bv[j] = Bs[k][tx * 4 + j];
#pragma unroll
            for (int i = 0; i < 4; i++)
#pragma unroll
                for (int j = 0; j < 4; j++) acc[i][j] += a[i] * bv[j];
        }
        __syncthreads();
    }
#pragma unroll
    for (int i = 0; i < 4; i++) {
#pragma unroll
        for (int j = 0; j < 4; j++) {
            int m = tm + ty * 4 + i;
            int n = tn + tx * 4 + j;
            float v = acc[i][j] + bias[n];
            if (mode == 3) {
                v = 0.5f * v * (1.0f + erff(v * 0.70710678118654752f));
                g_hidden[(size_t)m * HID + n] = v;
            } else {
                outp[(size_t)m * EM + n] = v;
            }
        }
    }
}

// ---------------- offset MLP layer 2: (4096,128)@(128,16)+b ------------------
__global__ void off2_kernel(const float* __restrict__ W2,
                            const float* __restrict__ b2) {
    int tid = threadIdx.x;
    int o = tid & 15;
    int r = tid >> 4;
    int row = blockIdx.x * 16 + r;
    float acc = b2[o];
    const float* hrow = &g_hidden[(size_t)row * HID];
#pragma unroll 8
    for (int k = 0; k < HID; k++) acc += hrow[k] * W2[k * 16 + o];
    g_off[(size_t)row * 16 + o] = acc;
}

// ---------------- scores: per-head Q @ K^T * scale, 128x128 tile -------------
__global__ __launch_bounds__(256) void scores_kernel() {
    __shared__ float Qs[128][36];
    __shared__ float Ks[128][36];
    int bh = blockIdx.z;
    int tm = blockIdx.x * 128;
    int tn = blockIdx.y * 128;
    const float* Q = g_q + (size_t)bh * SQ * HD;
    const float* K = g_k + (size_t)bh * SQ * HD;
    int tid = threadIdx.x;
#pragma unroll
    for (int q = 0; q < 4; q++) {
        int idx = q * 256 + tid;          // 0..1023 float4 slots
        int row = idx >> 3;
        int c4  = (idx & 7) * 4;
        *(float4*)&Qs[row][c4] = *(const float4*)&Q[(size_t)(tm + row) * HD + c4];
        *(float4*)&Ks[row][c4] = *(const float4*)&K[(size_t)(tn + row) * HD + c4];
    }
    __syncthreads();
    int tx = tid & 15, ty = tid >> 4;
    float acc[8][8] = {};
#pragma unroll
    for (int k = 0; k < 32; k++) {
        float a[8], bv[8];
#pragma unroll
        for (int i = 0; i < 8; i++) a[i] = Qs[ty * 8 + i][k];
#pragma unroll
        for (int j = 0; j < 8; j++) bv[j] = Ks[tx * 8 + j][k];
#pragma unroll
        for (int i = 0; i < 8; i++)
#pragma unroll
            for (int j = 0; j < 8; j++) acc[i][j] += a[i] * bv[j];
    }
    const float scale = 0.17677669529663687f;   // 1/sqrt(32)
    float* outr = g_scores + (size_t)bh * SQ * SQ;
#pragma unroll
    for (int i = 0; i < 8; i++) {
        float4 o0, o1;
        o0.x = acc[i][0] * scale; o0.y = acc[i][1] * scale;
        o0.z = acc[i][2] * scale; o0.w = acc[i][3] * scale;
        o1.x = acc[i][4] * scale; o1.y = acc[i][5] * scale;
        o1.z = acc[i][6] * scale; o1.w = acc[i][7] * scale;
        size_t base = (size_t)(tm + ty * 8 + i) * SQ + tn + tx * 8;
        *(float4*)&outr[base]     = o0;
        *(float4*)&outr[base + 4] = o1;
    }
}

// ------ fused: deform (bilinear on scores) + online softmax + @V -> g_att ----
__global__ __launch_bounds__(256) void fused_dsav_kernel() {
    __shared__ float Vs[64][32];       // V chunk
    __shared__ float Ls[64][65];       // logits -> probs (padded)
    __shared__ float row_ox[64], row_wy[64];
    __shared__ int   row_y0[64];
    __shared__ unsigned char row_vy0[64], row_vy1[64];
    __shared__ float m_s[64], s_s[64], f_s[64];
    __shared__ float red[64][4];

    int bh = blockIdx.y;
    int b = bh >> 3, h = bh & 7;
    int i0 = blockIdx.x * 64;
    int tid = threadIdx.x;

    if (tid < 64) {
        int i = i0 + tid;
        float ox = g_off[((size_t)(b * SQ + i)) * 16 + h * 2 + 0];
        float oy = g_off[((size_t)(b * SQ + i)) * 16 + h * 2 + 1];
        float ysf = (float)i + oy;
        float y0f = floorf(ysf);
        row_ox[tid] = ox;
        row_wy[tid] = ysf - y0f;
        row_y0[tid] = (int)y0f;
        row_vy0[tid] = (y0f >= 0.0f) && (y0f <= 1023.0f);
        row_vy1[tid] = (y0f >= -1.0f) && (y0f <= 1022.0f);
        m_s[tid] = -3.4e38f;
        s_s[tid] = 0.0f;
    }

    const float* sbase = g_scores + (size_t)bh * SQ * SQ;
    const float* V     = g_v + (size_t)bh * SQ * HD;

    int tx = tid & 7;        // 4 output cols: tx*4..tx*4+3
    int ty = tid >> 3;       // rows ty, ty+32
    float acc[2][4] = {};

    int jj = tid & 63;
    int rb = tid >> 6;       // 0..3

    for (int j0 = 0; j0 < SQ; j0 += 64) {
        __syncthreads();     // previous chunk's Ls/Vs fully consumed
        // load V chunk (2048 floats, 2 float4 / thread)
        {
            int r = tid >> 2;
            int c = (tid & 3) * 8;
            *(float4*)&Vs[r][c]     = *(const float4*)&V[(size_t)(j0 + r) * HD + c];
            *(float4*)&Vs[r][c + 4] = *(const float4*)&V[(size_t)(j0 + r) * HD + c + 4];
        }
        // compute deformed logits: 16 rows per thread, fixed column jj
#pragma unroll 4
        for (int q = 0; q < 16; q++) {
            int r = rb * 16 + q;
            float ox = row_ox[r];
            float xsf = (float)(j0 + jj) + ox;
            float x0f = floorf(xsf);
            float wx  = xsf - x0f;
            int   x0  = (int)x0f;
            bool vx0 = (x0f >= 0.0f)  && (x0f <= 1023.0f);
            bool vx1 = (x0f >= -1.0f) && (x0f <= 1022.0f);
            bool vy0 = row_vy0[r], vy1 = row_vy1[r];
            const float* r0 = sbase + (ptrdiff_t)row_y0[r] * SQ;
            float v00 = (vy0 && vx0) ? r0[x0]          : 0.0f;
            float v01 = (vy0 && vx1) ? r0[x0 + 1]      : 0.0f;
            float v10 = (vy1 && vx0) ? r0[x0 + SQ]     : 0.0f;
            float v11 = (vy1 && vx1) ? r0[x0 + 1 + SQ] : 0.0f;
            float wy = row_wy[r];
            Ls[r][jj] = v00 * (1.0f - wy) * (1.0f - wx)
                      + v01 * (1.0f - wy) * wx
                      + v10 * wy * (1.0f - wx)
                      + v11 * wy * wx;
        }
        __syncthreads();
        // per-row chunk max (4 segments of 16)
        {
            int r = tid >> 2, sg = tid & 3;
            float mx = -3.4e38f;
#pragma unroll
            for (int t = 0; t < 16; t++) mx = fmaxf(mx, Ls[r][sg * 16 + t]);
            red[r][sg] = mx;
        }
        __syncthreads();
        if (tid < 64) {
            float cm = fmaxf(fmaxf(red[tid][0], red[tid][1]),
                             fmaxf(red[tid][2], red[tid][3]));
            float m_old = m_s[tid];
            float m_new = fmaxf(m_old, cm);
            float f = __expf(m_old - m_new);
            f_s[tid] = f;
            s_s[tid] *= f;
            m_s[tid] = m_new;
        }
        __syncthreads();
        // exponentiate in place + partial sums
        {
            int r = tid >> 2, sg = tid & 3;
            float m = m_s[r];
            float sum = 0.0f;
#pragma unroll
            for (int t = 0; t < 16; t++) {
                float p = __expf(Ls[r][sg * 16 + t] - m);
                Ls[r][sg * 16 + t] = p;
                sum += p;
            }
            red[r][sg] = sum;
        }
        __syncthreads();
        if (tid < 64)
            s_s[tid] += red[tid][0] + red[tid][1] + red[tid][2] + red[tid][3];
        // rescale accumulators, then accumulate P @ V for this chunk
        {
            float f0 = f_s[ty], f1 = f_s[ty + 32];
#pragma unroll
            for (int c = 0; c < 4; c++) { acc[0][c] *= f0; acc[1][c] *= f1; }
#pragma unroll
            for (int k = 0; k < 64; k++) {
                float4 v = *(const float4*)&Vs[k][tx * 4];
                float p0 = Ls[ty][k];
                float p1 = Ls[ty + 32][k];
                acc[0][0] += p0 * v.x; acc[0][1] += p0 * v.y;
                acc[0][2] += p0 * v.z; acc[0][3] += p0 * v.w;
                acc[1][0] += p1 * v.x; acc[1][1] += p1 * v.y;
                acc[1][2] += p1 * v.z; acc[1][3] += p1 * v.w;
            }
        }
    }
    __syncthreads();
    {
        float inv0 = 1.0f / s_s[ty];
        float inv1 = 1.0f / s_s[ty + 32];
        int s0 = i0 + ty, s1 = i0 + ty + 32;
        float4 o0, o1;
        o0.x = acc[0][0] * inv0; o0.y = acc[0][1] * inv0;
        o0.z = acc[0][2] * inv0; o0.w = acc[0][3] * inv0;
        o1.x = acc[1][0] * inv1; o1.y = acc[1][1] * inv1;
        o1.z = acc[1][2] * inv1; o1.w = acc[1][3] * inv1;
        *(float4*)&g_att[((size_t)(b * SQ + s0)) * EM + h * HD + tx * 4] = o0;
        *(float4*)&g_att[((size_t)(b * SQ + s1)) * EM + h * HD + tx * 4] = o1;
    }
}

// ----------------------------- launcher --------------------------------------
extern "C" void kernel_launch(void* const* d_in, const int* in_sizes, int n_in,
                              void* d_out, int out_size) {
    const float* x      = (const float*)d_in[0];
    const float* Wq     = (const float*)d_in[1];
    const float* Wk     = (const float*)d_in[2];
    const float* Wv     = (const float*)d_in[3];
    const float* W_off1 = (const float*)d_in[4];
    const float* b_off1 = (const float*)d_in[5];
    const float* W_off2 = (const float*)d_in[6];
    const float* b_off2 = (const float*)d_in[7];
    const float* W_out  = (const float*)d_in[8];
    const float* b_out  = (const float*)d_in[9];
    float* out = (float*)d_out;

    // 1) QKV projections — single launch, z selects projection
    qkv_kernel<<<dim3(MROWS / 64, EM / 64, 3), 256>>>(x, Wq, Wk, Wv);

    // 2) offset MLP
    gemm64_kernel<<<dim3(MROWS / 64, HID / 64), 256>>>(x, W_off1, b_off1, nullptr, HID, 3);
    off2_kernel<<<MROWS / 16, 256>>>(W_off2, b_off2);

    // 3) scores = QK^T * scale (128x128 tiles)
    scores_kernel<<<dim3(SQ / 128, SQ / 128, BB * NH), 256>>>();

    // 4+5) fused deform + online softmax + @V
    fused_dsav_kernel<<<dim3(SQ / 64, BB * NH), 256>>>();

    // 6) output projection + bias
    gemm64_kernel<<<dim3(MROWS / 64, EM / 64), 256>>>(nullptr, W_out, b_out, out, EM, 4);
}

// round 13
// speedup vs baseline: 1.2320x; 1.2320x over previous
#include <cuda_runtime.h>
#include <math.h>
#include <stdint.h>
#include <stddef.h>

#define BB 4
#define SQ 1024
#define EM 256
#define NH 8
#define HD 32
#define MROWS (BB*SQ)          // 4096
#define HID 128                // MLP hidden

// ---------------- scratch (static device globals; allocation-free) ----------
__device__ float g_q[BB*NH*SQ*HD];                 // (b,h,s,d) 4 MB
__device__ float g_k[BB*NH*SQ*HD];
__device__ float g_v[BB*NH*SQ*HD];
__device__ float g_hidden[MROWS*HID];              // 2 MB
__device__ float g_off[MROWS*NH*2];                // (b*S+s)*16 + h*2 + {x,y}
__device__ float g_scores[(size_t)BB*NH*SQ*SQ];    // 128 MB
__device__ float g_att[MROWS*EM];                  // (b,s, h*32+d) 4 MB

// ---------------- QKV: one launch, z picks projection ------------------------
// A-tile stored k-major (transposed) -> conflict-free float4 fragment loads.
__global__ __launch_bounds__(256) void qkv_kernel(const float* __restrict__ A,
                                                  const float* __restrict__ Wq,
                                                  const float* __restrict__ Wk,
                                                  const float* __restrict__ Wv) {
    __shared__ float As[16][68];   // [k][m], padded
    __shared__ float Bs[16][64];   // [k][n]
    const float* W = (blockIdx.z == 0) ? Wq : (blockIdx.z == 1) ? Wk : Wv;
    float* scat    = (blockIdx.z == 0) ? g_q : (blockIdx.z == 1) ? g_k : g_v;
    int tm = blockIdx.x * 64;
    int tn = blockIdx.y * 64;
    int tid = threadIdx.x;
    int tx = tid & 15, ty = tid >> 4;
    float acc[4][4] = {};
    for (int k0 = 0; k0 < EM; k0 += 16) {
        int m  = tid >> 2;
        int kb = (tid & 3) * 4;
        float4 av = *(const float4*)&A[(size_t)(tm + m) * EM + k0 + kb];
        As[kb + 0][m] = av.x; As[kb + 1][m] = av.y;
        As[kb + 2][m] = av.z; As[kb + 3][m] = av.w;
        int kk = tid >> 4;
        int nb = (tid & 15) * 4;
        *(float4*)&Bs[kk][nb] = *(const float4*)&W[(size_t)(k0 + kk) * EM + tn + nb];
        __syncthreads();
#pragma unroll
        for (int k = 0; k < 16; k++) {
            float4 a  = *(const float4*)&As[k][ty * 4];
            float4 bv = *(const float4*)&Bs[k][tx * 4];
            float ar[4] = {a.x, a.y, a.z, a.w};
            float br[4] = {bv.x, bv.y, bv.z, bv.w};
#pragma unroll
            for (int i = 0; i < 4; i++)
#pragma unroll
                for (int j = 0; j < 4; j++) acc[i][j] += ar[i] * br[j];
        }
        __syncthreads();
    }
#pragma unroll
    for (int i = 0; i < 4; i++) {
#pragma unroll
        for (int j = 0; j < 4; j++) {
            int m = tm + ty * 4 + i;
            int n = tn + tx * 4 + j;
            int b = m >> 10, s = m & 1023, h = n >> 5, d = n & 31;
            scat[(((size_t)(b * NH + h)) * SQ + s) * HD + d] = acc[i][j];
        }
    }
}

// ---------------- generic 64x64 GEMM (hidden-GELU / out-proj) ----------------
// mode 3: out = gelu(x@W + bias) -> g_hidden   (N=128)
// mode 4: out = g_att@W + bias -> outp         (N=256)
__global__ __launch_bounds__(256) void gemm64_kernel(const float* __restrict__ A,
                              const float* __restrict__ W,
                              const float* __restrict__ bias,
                              float* __restrict__ outp,
                              int N, int mode) {
    __shared__ float As[16][68];
    __shared__ float Bs[16][64];
    const float* Ap = (mode == 4) ? g_att : A;
    int tm = blockIdx.x * 64;
    int tn = blockIdx.y * 64;
    int tid = threadIdx.x;
    int tx = tid & 15, ty = tid >> 4;
    float acc[4][4] = {};
    for (int k0 = 0; k0 < EM; k0 += 16) {
        int m  = tid >> 2;
        int kb = (tid & 3) * 4;
        float4 av = *(const float4*)&Ap[(size_t)(tm + m) * EM + k0 + kb];
        As[kb + 0][m] = av.x; As[kb + 1][m] = av.y;
        As[kb + 2][m] = av.z; As[kb + 3][m] = av.w;
        int kk = tid >> 4;
        int nb = (tid & 15) * 4;
        *(float4*)&Bs[kk][nb] = *(const float4*)&W[(size_t)(k0 + kk) * N + tn + nb];
        __syncthreads();
#pragma unroll
        for (int k = 0; k < 16; k++) {
            float4 a  = *(const float4*)&As[k][ty * 4];
            float4 bv = *(const float4*)&Bs[k][tx * 4];
            float ar[4] = {a.x, a.y, a.z, a.w};
            float br[4] = {bv.x, bv.y, bv.z, bv.w};
#pragma unroll
            for (int i = 0; i < 4; i++)
#pragma unroll
                for (int j = 0; j < 4; j++) acc[i][j] += ar[i] * br[j];
        }
        __syncthreads();
    }
#pragma unroll
    for (int i = 0; i < 4; i++) {
#pragma unroll
        for (int j = 0; j < 4; j++) {
            int m = tm + ty * 4 + i;
            int n = tn + tx * 4 + j;
            float v = acc[i][j] + bias[n];
            if (mode == 3) {
                v = 0.5f * v * (1.0f + erff(v * 0.70710678118654752f));
                g_hidden[(size_t)m * HID + n] = v;
            } else {
                outp[(size_t)m * EM + n] = v;
            }
        }
    }
}

// ---------------- offset MLP layer 2: (4096,128)@(128,16)+b ------------------
__global__ void off2_kernel(const float* __restrict__ W2,
                            const float* __restrict__ b2) {
    int tid = threadIdx.x;
    int o = tid & 15;
    int r = tid >> 4;
    int row = blockIdx.x * 16 + r;
    float acc = b2[o];
    const float* hrow = &g_hidden[(size_t)row * HID];
#pragma unroll 8
    for (int k = 0; k < HID; k++) acc += hrow[k] * W2[k * 16 + o];
    g_off[(size_t)row * 16 + o] = acc;
}

// ---------------- scores: per-head Q @ K^T * scale, 128x128 tile -------------
// k-major smem tiles: fragment loads are conflict-free LDS.128.
__global__ __launch_bounds__(256, 2) void scores_kernel() {
    __shared__ float Qs[32][132];   // [k][row], pad 132 (132%32==4)
    __shared__ float Ks[32][132];
    int bh = blockIdx.z;
    int tm = blockIdx.x * 128;
    int tn = blockIdx.y * 128;
    const float* Q = g_q + (size_t)bh * SQ * HD;
    const float* K = g_k + (size_t)bh * SQ * HD;
    int tid = threadIdx.x;
#pragma unroll
    for (int q = 0; q < 4; q++) {
        int idx = q * 256 + tid;          // 0..1023 float4 slots
        int row = idx >> 3;
        int c4  = (idx & 7) * 4;
        float4 a = *(const float4*)&Q[(size_t)(tm + row) * HD + c4];
        Qs[c4 + 0][row] = a.x; Qs[c4 + 1][row] = a.y;
        Qs[c4 + 2][row] = a.z; Qs[c4 + 3][row] = a.w;
        float4 b = *(const float4*)&K[(size_t)(tn + row) * HD + c4];
        Ks[c4 + 0][row] = b.x; Ks[c4 + 1][row] = b.y;
        Ks[c4 + 2][row] = b.z; Ks[c4 + 3][row] = b.w;
    }
    __syncthreads();
    int tx = tid & 15, ty = tid >> 4;
    float acc[8][8] = {};
#pragma unroll
    for (int k = 0; k < 32; k++) {
        float4 a0 = *(const float4*)&Qs[k][ty * 8];
        float4 a1 = *(const float4*)&Qs[k][ty * 8 + 4];
        float4 b0 = *(const float4*)&Ks[k][tx * 8];
        float4 b1 = *(const float4*)&Ks[k][tx * 8 + 4];
        float a[8] = {a0.x, a0.y, a0.z, a0.w, a1.x, a1.y, a1.z, a1.w};
        float bv[8] = {b0.x, b0.y, b0.z, b0.w, b1.x, b1.y, b1.z, b1.w};
#pragma unroll
        for (int i = 0; i < 8; i++)
#pragma unroll
            for (int j = 0; j < 8; j++) acc[i][j] += a[i] * bv[j];
    }
    const float scale = 0.17677669529663687f;   // 1/sqrt(32)
    float* outr = g_scores + (size_t)bh * SQ * SQ;
#pragma unroll
    for (int i = 0; i < 8; i++) {
        float4 o0, o1;
        o0.x = acc[i][0] * scale; o0.y = acc[i][1] * scale;
        o0.z = acc[i][2] * scale; o0.w = acc[i][3] * scale;
        o1.x = acc[i][4] * scale; o1.y = acc[i][5] * scale;
        o1.z = acc[i][6] * scale; o1.w = acc[i][7] * scale;
        size_t base = (size_t)(tm + ty * 8 + i) * SQ + tn + tx * 8;
        *(float4*)&outr[base]     = o0;
        *(float4*)&outr[base + 4] = o1;
    }
}

// ------ fused: deform (bilinear on scores) + online softmax + @V -> g_att ----
__global__ __launch_bounds__(256) void fused_dsav_kernel() {
    __shared__ float Vs[64][32];       // V chunk
    __shared__ float Ls[64][65];       // logits -> probs (padded)
    __shared__ float row_ox[64], row_wy[64];
    __shared__ int   row_y0[64];
    __shared__ unsigned char row_vy0[64], row_vy1[64];
    __shared__ float m_s[64], s_s[64], f_s[64];
    __shared__ float red[64][4];

    int bh = blockIdx.y;
    int b = bh >> 3, h = bh & 7;
    int i0 = blockIdx.x * 64;
    int tid = threadIdx.x;

    if (tid < 64) {
        int i = i0 + tid;
        float ox = g_off[((size_t)(b * SQ + i)) * 16 + h * 2 + 0];
        float oy = g_off[((size_t)(b * SQ + i)) * 16 + h * 2 + 1];
        float ysf = (float)i + oy;
        float y0f = floorf(ysf);
        row_ox[tid] = ox;
        row_wy[tid] = ysf - y0f;
        row_y0[tid] = (int)y0f;
        row_vy0[tid] = (y0f >= 0.0f) && (y0f <= 1023.0f);
        row_vy1[tid] = (y0f >= -1.0f) && (y0f <= 1022.0f);
        m_s[tid] = -3.4e38f;
        s_s[tid] = 0.0f;
    }

    const float* sbase = g_scores + (size_t)bh * SQ * SQ;
    const float* V     = g_v + (size_t)bh * SQ * HD;

    int tx = tid & 7;        // 4 output cols: tx*4..tx*4+3
    int ty = tid >> 3;       // rows ty, ty+32
    float acc[2][4] = {};

    int jj = tid & 63;
    int rb = tid >> 6;       // 0..3

    for (int j0 = 0; j0 < SQ; j0 += 64) {
        __syncthreads();     // previous chunk's Ls/Vs fully consumed
        // load V chunk (2048 floats, 2 float4 / thread)
        {
            int r = tid >> 2;
            int c = (tid & 3) * 8;
            *(float4*)&Vs[r][c]     = *(const float4*)&V[(size_t)(j0 + r) * HD + c];
            *(float4*)&Vs[r][c + 4] = *(const float4*)&V[(size_t)(j0 + r) * HD + c + 4];
        }
        // compute deformed logits: 16 rows per thread, fixed column jj
#pragma unroll 4
        for (int q = 0; q < 16; q++) {
            int r = rb * 16 + q;
            float ox = row_ox[r];
            float xsf = (float)(j0 + jj) + ox;
            float x0f = floorf(xsf);
            float wx  = xsf - x0f;
            int   x0  = (int)x0f;
            bool vx0 = (x0f >= 0.0f)  && (x0f <= 1023.0f);
            bool vx1 = (x0f >= -1.0f) && (x0f <= 1022.0f);
            bool vy0 = row_vy0[r], vy1 = row_vy1[r];
            const float* r0 = sbase + (ptrdiff_t)row_y0[r] * SQ;
            float v00 = (vy0 && vx0) ? r0[x0]          : 0.0f;
            float v01 = (vy0 && vx1) ? r0[x0 + 1]      : 0.0f;
            float v10 = (vy1 && vx0) ? r0[x0 + SQ]     : 0.0f;
            float v11 = (vy1 && vx1) ? r0[x0 + 1 + SQ] : 0.0f;
            float wy = row_wy[r];
            Ls[r][jj] = v00 * (1.0f - wy) * (1.0f - wx)
                      + v01 * (1.0f - wy) * wx
                      + v10 * wy * (1.0f - wx)
                      + v11 * wy * wx;
        }
        __syncthreads();
        // per-row chunk max (4 segments of 16)
        {
            int r = tid >> 2, sg = tid & 3;
            float mx = -3.4e38f;
#pragma unroll
            for (int t = 0; t < 16; t++) mx = fmaxf(mx, Ls[r][sg * 16 + t]);
            red[r][sg] = mx;
        }
        __syncthreads();
        if (tid < 64) {
            float cm = fmaxf(fmaxf(red[tid][0], red[tid][1]),
                             fmaxf(red[tid][2], red[tid][3]));
            float m_old = m_s[tid];
            float m_new = fmaxf(m_old, cm);
            float f = __expf(m_old - m_new);
            f_s[tid] = f;
            s_s[tid] *= f;
            m_s[tid] = m_new;
        }
        __syncthreads();
        // exponentiate in place + partial sums
        {
            int r = tid >> 2, sg = tid & 3;
            float m = m_s[r];
            float sum = 0.0f;
#pragma unroll
            for (int t = 0; t < 16; t++) {
                float p = __expf(Ls[r][sg * 16 + t] - m);
                Ls[r][sg * 16 + t] = p;
                sum += p;
            }
            red[r][sg] = sum;
        }
        __syncthreads();
        if (tid < 64)
            s_s[tid] += red[tid][0] + red[tid][1] + red[tid][2] + red[tid][3];
        // rescale accumulators, then accumulate P @ V for this chunk
        {
            float f0 = f_s[ty], f1 = f_s[ty + 32];
#pragma unroll
            for (int c = 0; c < 4; c++) { acc[0][c] *= f0; acc[1][c] *= f1; }
#pragma unroll
            for (int k = 0; k < 64; k++) {
                float4 v = *(const float4*)&Vs[k][tx * 4];
                float p0 = Ls[ty][k];
                float p1 = Ls[ty + 32][k];
                acc[0][0] += p0 * v.x; acc[0][1] += p0 * v.y;
                acc[0][2] += p0 * v.z; acc[0][3] += p0 * v.w;
                acc[1][0] += p1 * v.x; acc[1][1] += p1 * v.y;
                acc[1][2] += p1 * v.z; acc[1][3] += p1 * v.w;
            }
        }
    }
    __syncthreads();
    {
        float inv0 = 1.0f / s_s[ty];
        float inv1 = 1.0f / s_s[ty + 32];
        int s0 = i0 + ty, s1 = i0 + ty + 32;
        float4 o0, o1;
        o0.x = acc[0][0] * inv0; o0.y = acc[0][1] * inv0;
        o0.z = acc[0][2] * inv0; o0.w = acc[0][3] * inv0;
        o1.x = acc[1][0] * inv1; o1.y = acc[1][1] * inv1;
        o1.z = acc[1][2] * inv1; o1.w = acc[1][3] * inv1;
        *(float4*)&g_att[((size_t)(b * SQ + s0)) * EM + h * HD + tx * 4] = o0;
        *(float4*)&g_att[((size_t)(b * SQ + s1)) * EM + h * HD + tx * 4] = o1;
    }
}

// ----------------------------- launcher --------------------------------------
extern "C" void kernel_launch(void* const* d_in, const int* in_sizes, int n_in,
                              void* d_out, int out_size) {
    const float* x      = (const float*)d_in[0];
    const float* Wq     = (const float*)d_in[1];
    const float* Wk     = (const float*)d_in[2];
    const float* Wv     = (const float*)d_in[3];
    const float* W_off1 = (const float*)d_in[4];
    const float* b_off1 = (const float*)d_in[5];
    const float* W_off2 = (const float*)d_in[6];
    const float* b_off2 = (const float*)d_in[7];
    const float* W_out  = (const float*)d_in[8];
    const float* b_out  = (const float*)d_in[9];
    float* out = (float*)d_out;

    // 1) QKV projections — single launch, z selects projection
    qkv_kernel<<<dim3(MROWS / 64, EM / 64, 3), 256>>>(x, Wq, Wk, Wv);

    // 2) offset MLP
    gemm64_kernel<<<dim3(MROWS / 64, HID / 64), 256>>>(x, W_off1, b_off1, nullptr, HID, 3);
    off2_kernel<<<MROWS / 16, 256>>>(W_off2, b_off2);

    // 3) scores = QK^T * scale (128x128 tiles, k-major smem)
    scores_kernel<<<dim3(SQ / 128, SQ / 128, BB * NH), 256>>>();

    // 4+5) fused deform + online softmax + @V
    fused_dsav_kernel<<<dim3(SQ / 64, BB * NH), 256>>>();

    // 6) output projection + bias
    gemm64_kernel<<<dim3(MROWS / 64, EM / 64), 256>>>(nullptr, W_out, b_out, out, EM, 4);
}

// round 15
// speedup vs baseline: 1.2512x; 1.0156x over previous
#include <cuda_runtime.h>
#include <math.h>
#include <stdint.h>
#include <stddef.h>

#define BB 4
#define SQ 1024
#define EM 256
#define NH 8
#define HD 32
#define MROWS (BB*SQ)          // 4096
#define HID 128                // MLP hidden

#define KSTR 84                // Zs / K-window column stride (16B-aligned, conflict pad)
#define QSTR 68                // Qe column stride
#define NCW_CAP 81             // K/Z window capacity (offset spread <= 16 fast path)

// ---------------- scratch (static device globals; allocation-free) ----------
__device__ float g_q[BB*NH*SQ*HD];                 // (b,h,s,d) 4 MB
__device__ float g_k[BB*NH*SQ*HD];
__device__ float g_v[BB*NH*SQ*HD];
__device__ float g_hidden[MROWS*HID];              // 2 MB
__device__ float g_off[MROWS*NH*2];                // (b*S+s)*16 + h*2 + {x,y}
__device__ float g_att[MROWS*EM];                  // (b,s, h*32+d) 4 MB

// ---------------- QKV: one launch, z picks projection ------------------------
__global__ __launch_bounds__(256) void qkv_kernel(const float* __restrict__ A,
                                                  const float* __restrict__ Wq,
                                                  const float* __restrict__ Wk,
                                                  const float* __restrict__ Wv) {
    __shared__ float As[16][68];   // [k][m], padded
    __shared__ float Bs[16][64];   // [k][n]
    const float* W = (blockIdx.z == 0) ? Wq : (blockIdx.z == 1) ? Wk : Wv;
    float* scat    = (blockIdx.z == 0) ? g_q : (blockIdx.z == 1) ? g_k : g_v;
    int tm = blockIdx.x * 64;
    int tn = blockIdx.y * 64;
    int tid = threadIdx.x;
    int tx = tid & 15, ty = tid >> 4;
    float acc[4][4] = {};
    for (int k0 = 0; k0 < EM; k0 += 16) {
        int m  = tid >> 2;
        int kb = (tid & 3) * 4;
        float4 av = *(const float4*)&A[(size_t)(tm + m) * EM + k0 + kb];
        As[kb + 0][m] = av.x; As[kb + 1][m] = av.y;
        As[kb + 2][m] = av.z; As[kb + 3][m] = av.w;
        int kk = tid >> 4;
        int nb = (tid & 15) * 4;
        *(float4*)&Bs[kk][nb] = *(const float4*)&W[(size_t)(k0 + kk) * EM + tn + nb];
        __syncthreads();
#pragma unroll
        for (int k = 0; k < 16; k++) {
            float4 a  = *(const float4*)&As[k][ty * 4];
            float4 bv = *(const float4*)&Bs[k][tx * 4];
            float ar[4] = {a.x, a.y, a.z, a.w};
            float br[4] = {bv.x, bv.y, bv.z, bv.w};
#pragma unroll
            for (int i = 0; i < 4; i++)
#pragma unroll
                for (int j = 0; j < 4; j++) acc[i][j] += ar[i] * br[j];
        }
        __syncthreads();
    }
#pragma unroll
    for (int i = 0; i < 4; i++) {
#pragma unroll
        for (int j = 0; j < 4; j++) {
            int m = tm + ty * 4 + i;
            int n = tn + tx * 4 + j;
            int b = m >> 10, s = m & 1023, h = n >> 5, d = n & 31;
            scat[(((size_t)(b * NH + h)) * SQ + s) * HD + d] = acc[i][j];
        }
    }
}

// ---------------- generic 64x64 GEMM (hidden-GELU / out-proj) ----------------
__global__ __launch_bounds__(256) void gemm64_kernel(const float* __restrict__ A,
                              const float* __restrict__ W,
                              const float* __restrict__ bias,
                              float* __restrict__ outp,
                              int N, int mode) {
    __shared__ float As[16][68];
    __shared__ float Bs[16][64];
    const float* Ap = (mode == 4) ? g_att : A;
    int tm = blockIdx.x * 64;
    int tn = blockIdx.y * 64;
    int tid = threadIdx.x;
    int tx = tid & 15, ty = tid >> 4;
    float acc[4][4] = {};
    for (int k0 = 0; k0 < EM; k0 += 16) {
        int m  = tid >> 2;
        int kb = (tid & 3) * 4;
        float4 av = *(const float4*)&Ap[(size_t)(tm + m) * EM + k0 + kb];
        As[kb + 0][m] = av.x; As[kb + 1][m] = av.y;
        As[kb + 2][m] = av.z; As[kb + 3][m] = av.w;
        int kk = tid >> 4;
        int nb = (tid & 15) * 4;
        *(float4*)&Bs[kk][nb] = *(const float4*)&W[(size_t)(k0 + kk) * N + tn + nb];
        __syncthreads();
#pragma unroll
        for (int k = 0; k < 16; k++) {
            float4 a  = *(const float4*)&As[k][ty * 4];
            float4 bv = *(const float4*)&Bs[k][tx * 4];
            float ar[4] = {a.x, a.y, a.z, a.w};
            float br[4] = {bv.x, bv.y, bv.z, bv.w};
#pragma unroll
            for (int i = 0; i < 4; i++)
#pragma unroll
                for (int j = 0; j < 4; j++) acc[i][j] += ar[i] * br[j];
        }
        __syncthreads();
    }
#pragma unroll
    for (int i = 0; i < 4; i++) {
#pragma unroll
        for (int j = 0; j < 4; j++) {
            int m = tm + ty * 4 + i;
            int n = tn + tx * 4 + j;
            float v = acc[i][j] + bias[n];
            if (mode == 3) {
                v = 0.5f * v * (1.0f + erff(v * 0.70710678118654752f));
                g_hidden[(size_t)m * HID + n] = v;
            } else {
                outp[(size_t)m * EM + n] = v;
            }
        }
    }
}

// ---------------- offset MLP layer 2: (4096,128)@(128,16)+b ------------------
__global__ void off2_kernel(const float* __restrict__ W2,
                            const float* __restrict__ b2) {
    int tid = threadIdx.x;
    int o = tid & 15;
    int r = tid >> 4;
    int row = blockIdx.x * 16 + r;
    float acc = b2[o];
    const float* hrow = &g_hidden[(size_t)row * HID];
#pragma unroll 8
    for (int k = 0; k < HID; k++) acc += hrow[k] * W2[k * 16 + o];
    g_off[(size_t)row * 16 + o] = acc;
}

// ---- guarded global fallback dot (only if offset spread > 16; never in practice)
__device__ __forceinline__ float gdot(const float* __restrict__ Kb, int x, int r,
                                      const float* __restrict__ Qe) {
    if (x < 0 || x >= SQ) return 0.0f;
    float s = 0.0f;
#pragma unroll 8
    for (int k = 0; k < 32; k++) s += Qe[k * QSTR + r] * Kb[(size_t)x * HD + k];
    return s;
}

// ------ fused flash kernel: Qeff build + Z GEMM + shift-combine + softmax + PV
// logit[i,j] = (1-wx_i)*Z[i, j+ci] + wx_i*Z[i, j+ci+1],  Z[i,x] = Qeff[i]·K[x]
// Qeff[i] = scale * ((1-wy)*vy0*Q[y0] + wy*vy1*Q[y0+1]);  Z zero-padded in x.
__global__ __launch_bounds__(256, 2) void fused_flash_kernel() {
    __shared__ float Zs[64 * KSTR];     // Z tile, later probs (21.5 KB)
    __shared__ float KV[32 * KSTR];     // K window (k-major), later V chunk (10.8 KB)
    __shared__ float Qe[32 * QSTR];     // Qeff k-major (8.7 KB)
    __shared__ float row_wx[64], row_w0[64], row_w1[64];
    __shared__ int   row_ci[64], row_y0[64];
    __shared__ float m_s[64], s_s[64], f_s[64];
    __shared__ float red[64][4];
    __shared__ int s_cmin, s_cmax;

    int bh = blockIdx.y;
    int b = bh >> 3, h = bh & 7;
    int i0 = blockIdx.x * 64;
    int tid = threadIdx.x;

    if (tid == 0) { s_cmin = 0x7fffffff; s_cmax = -0x7fffffff; }
    __syncthreads();

    if (tid < 64) {
        int i = i0 + tid;
        float ox = g_off[((size_t)(b * SQ + i)) * 16 + h * 2 + 0];
        float oy = g_off[((size_t)(b * SQ + i)) * 16 + h * 2 + 1];
        float cxf = floorf(ox); float wx = ox - cxf; int ci = (int)cxf;
        float cyf = floorf(oy); float wy = oy - cyf;
        int y0 = i + (int)cyf;
        bool vy0 = (y0 >= 0) && (y0 <= SQ - 1);
        bool vy1 = (y0 >= -1) && (y0 <= SQ - 2);
        const float scale = 0.17677669529663687f;   // 1/sqrt(32)
        row_wx[tid] = wx;
        row_ci[tid] = ci;
        row_y0[tid] = y0;
        row_w0[tid] = vy0 ? scale * (1.0f - wy) : 0.0f;
        row_w1[tid] = vy1 ? scale * wy : 0.0f;
        m_s[tid] = -3.4e38f;
        s_s[tid] = 0.0f;
        atomicMin(&s_cmin, ci);
        atomicMax(&s_cmax, ci);
    }
    __syncthreads();

    // build Qeff k-major: 4 threads per row, 8 k's each
    {
        int r  = tid >> 2;
        int kq = (tid & 3) * 8;
        int y0 = row_y0[r];
        float w0 = row_w0[r], w1 = row_w1[r];
        const float* Qb = g_q + (size_t)bh * SQ * HD;
        float q0[8] = {0,0,0,0,0,0,0,0}, q1[8] = {0,0,0,0,0,0,0,0};
        if (w0 != 0.0f && y0 >= 0 && y0 < SQ) {
            float4 a = *(const float4*)&Qb[(size_t)y0 * HD + kq];
            float4 c = *(const float4*)&Qb[(size_t)y0 * HD + kq + 4];
            q0[0]=a.x; q0[1]=a.y; q0[2]=a.z; q0[3]=a.w;
            q0[4]=c.x; q0[5]=c.y; q0[6]=c.z; q0[7]=c.w;
        }
        if (w1 != 0.0f && (y0 + 1) >= 0 && (y0 + 1) < SQ) {
            float4 a = *(const float4*)&Qb[(size_t)(y0 + 1) * HD + kq];
            float4 c = *(const float4*)&Qb[(size_t)(y0 + 1) * HD + kq + 4];
            q1[0]=a.x; q1[1]=a.y; q1[2]=a.z; q1[3]=a.w;
            q1[4]=c.x; q1[5]=c.y; q1[6]=c.z; q1[7]=c.w;
        }
#pragma unroll
        for (int t = 0; t < 8; t++)
            Qe[(kq + t) * QSTR + r] = w0 * q0[t] + w1 * q1[t];
    }
    __syncthreads();

    int cmin = s_cmin;
    int ncols = (s_cmax - cmin) + 65;            // needed Z columns per chunk
    if (ncols < 65) ncols = 65;
    int ncw = ncols < NCW_CAP ? ncols : NCW_CAP; // smem-covered columns

    const float* Kb = g_k + (size_t)bh * SQ * HD;
    const float* Vb = g_v + (size_t)bh * SQ * HD;

    int tx4 = tid & 15, ty4 = tid >> 4;   // Z GEMM map (4x4 each)
    int jj  = tid & 63, rb  = tid >> 6;   // logit map (16 rows x 1 col)
    int txv = tid & 7,  tyv = tid >> 3;   // PV map (2 rows x 4 d)
    float acc[2][4] = {};

    for (int j0 = 0; j0 < SQ; j0 += 64) {
        int xlo = j0 + cmin;
        __syncthreads();   // prev chunk fully consumed (Zs, KV free)

        // A: K window -> KV (k-major), zero-padded outside [0,1023]
        for (int idx = tid; idx < ncw * 8; idx += 256) {
            int col = idx >> 3;
            int kq  = (idx & 7) * 4;
            int x = xlo + col;
            float4 kv4 = make_float4(0.f, 0.f, 0.f, 0.f);
            if (x >= 0 && x < SQ) kv4 = *(const float4*)&Kb[(size_t)x * HD + kq];
            KV[(kq + 0) * KSTR + col] = kv4.x;
            KV[(kq + 1) * KSTR + col] = kv4.y;
            KV[(kq + 2) * KSTR + col] = kv4.z;
            KV[(kq + 3) * KSTR + col] = kv4.w;
        }
        __syncthreads();

        // B: main Z tile (cols 0..63): Qeff(64x32) @ Kwin(32x64)
        {
            float za[4][4] = {};
#pragma unroll
            for (int k = 0; k < 32; k++) {
                float4 a  = *(const float4*)&Qe[k * QSTR + ty4 * 4];
                float4 bv = *(const float4*)&KV[k * KSTR + tx4 * 4];
                float ar[4] = {a.x, a.y, a.z, a.w};
                float br[4] = {bv.x, bv.y, bv.z, bv.w};
#pragma unroll
                for (int i = 0; i < 4; i++)
#pragma unroll
                    for (int j = 0; j < 4; j++) za[i][j] += ar[i] * br[j];
            }
#pragma unroll
            for (int i = 0; i < 4; i++) {
                float4 o; o.x = za[i][0]; o.y = za[i][1]; o.z = za[i][2]; o.w = za[i][3];
                *(float4*)&Zs[(ty4 * 4 + i) * KSTR + tx4 * 4] = o;
            }
        }
        // C: extra columns 64..ncw-1 (per-dot; tiny count)
        {
            int cnt = ncw - 64;
            for (int idx = tid; idx < 64 * cnt; idx += 256) {
                int r = idx & 63;
                int col = 64 + (idx >> 6);
                float s = 0.0f;
#pragma unroll 8
                for (int k = 0; k < 32; k++) s += Qe[k * QSTR + r] * KV[k * KSTR + col];
                Zs[r * KSTR + col] = s;
            }
        }
        __syncthreads();

        // D1: logits into registers (reads Zs); V chunk load overlaps (KV dead)
        float L16[16];
#pragma unroll
        for (int q = 0; q < 16; q++) {
            int r = rb * 16 + q;
            int zc = jj + row_ci[r] - cmin;
            float z0, z1;
            if (zc + 1 <= ncw - 1) {
                z0 = Zs[r * KSTR + zc];
                z1 = Zs[r * KSTR + zc + 1];
            } else {   // offset spread beyond smem window: recompute from global
                z0 = (zc <= ncw - 1) ? Zs[r * KSTR + zc] : gdot(Kb, xlo + zc, r, Qe);
                z1 = gdot(Kb, xlo + zc + 1, r, Qe);
            }
            float wx = row_wx[r];
            L16[q] = (1.0f - wx) * z0 + wx * z1;
        }
        {
            int r = tid >> 2;
            int c = (tid & 3) * 8;
            *(float4*)&KV[r * 32 + c]     = *(const float4*)&Vb[(size_t)(j0 + r) * HD + c];
            *(float4*)&KV[r * 32 + c + 4] = *(const float4*)&Vb[(size_t)(j0 + r) * HD + c + 4];
        }
        __syncthreads();   // all Zs reads complete

        // D2: store logits into Zs region (now acting as Ls/probs)
#pragma unroll
        for (int q = 0; q < 16; q++) Zs[(rb * 16 + q) * KSTR + jj] = L16[q];
        __syncthreads();

        // chunk max per row
        {
            int r = tid >> 2, sg = tid & 3;
            float mx = -3.4e38f;
#pragma unroll
            for (int t = 0; t < 16; t++) mx = fmaxf(mx, Zs[r * KSTR + sg * 16 + t]);
            red[r][sg] = mx;
        }
        __syncthreads();
        if (tid < 64) {
            float cm = fmaxf(fmaxf(red[tid][0], red[tid][1]),
                             fmaxf(red[tid][2], red[tid][3]));
            float m_old = m_s[tid];
            float m_new = fmaxf(m_old, cm);
            float f = __expf(m_old - m_new);
            f_s[tid] = f;
            s_s[tid] *= f;
            m_s[tid] = m_new;
        }
        __syncthreads();
        // exponentiate in place + partial sums
        {
            int r = tid >> 2, sg = tid & 3;
            float m = m_s[r];
            float sum = 0.0f;
#pragma unroll
            for (int t = 0; t < 16; t++) {
                float p = __expf(Zs[r * KSTR + sg * 16 + t] - m);
                Zs[r * KSTR + sg * 16 + t] = p;
                sum += p;
            }
            red[r][sg] = sum;
        }
        __syncthreads();
        if (tid < 64)
            s_s[tid] += red[tid][0] + red[tid][1] + red[tid][2] + red[tid][3];
        // PV accumulate (probs in Zs, V in KV)
        {
            float f0 = f_s[tyv], f1 = f_s[tyv + 32];
#pragma unroll
            for (int c = 0; c < 4; c++) { acc[0][c] *= f0; acc[1][c] *= f1; }
#pragma unroll
            for (int k = 0; k < 64; k++) {
                float4 v = *(const float4*)&KV[k * 32 + txv * 4];
                float p0 = Zs[tyv * KSTR + k];
                float p1 = Zs[(tyv + 32) * KSTR + k];
                acc[0][0] += p0 * v.x; acc[0][1] += p0 * v.y;
                acc[0][2] += p0 * v.z; acc[0][3] += p0 * v.w;
                acc[1][0] += p1 * v.x; acc[1][1] += p1 * v.y;
                acc[1][2] += p1 * v.z; acc[1][3] += p1 * v.w;
            }
        }
    }
    __syncthreads();
    {
        float inv0 = 1.0f / s_s[tyv];
        float inv1 = 1.0f / s_s[tyv + 32];
        int s0 = i0 + tyv, s1 = i0 + tyv + 32;
        float4 o0, o1;
        o0.x = acc[0][0] * inv0; o0.y = acc[0][1] * inv0;
        o0.z = acc[0][2] * inv0; o0.w = acc[0][3] * inv0;
        o1.x = acc[1][0] * inv1; o1.y = acc[1][1] * inv1;
        o1.z = acc[1][2] * inv1; o1.w = acc[1][3] * inv1;
        *(float4*)&g_att[((size_t)(b * SQ + s0)) * EM + h * HD + txv * 4] = o0;
        *(float4*)&g_att[((size_t)(b * SQ + s1)) * EM + h * HD + txv * 4] = o1;
    }
}

// ----------------------------- launcher --------------------------------------
extern "C" void kernel_launch(void* const* d_in, const int* in_sizes, int n_in,
                              void* d_out, int out_size) {
    const float* x      = (const float*)d_in[0];
    const float* Wq     = (const float*)d_in[1];
    const float* Wk     = (const float*)d_in[2];
    const float* Wv     = (const float*)d_in[3];
    const float* W_off1 = (const float*)d_in[4];
    const float* b_off1 = (const float*)d_in[5];
    const float* W_off2 = (const float*)d_in[6];
    const float* b_off2 = (const float*)d_in[7];
    const float* W_out  = (const float*)d_in[8];
    const float* b_out  = (const float*)d_in[9];
    float* out = (float*)d_out;

    // 1) QKV projections — single launch, z selects projection
    qkv_kernel<<<dim3(MROWS / 64, EM / 64, 3), 256>>>(x, Wq, Wk, Wv);

    // 2) offset MLP
    gemm64_kernel<<<dim3(MROWS / 64, HID / 64), 256>>>(x, W_off1, b_off1, nullptr, HID, 3);
    off2_kernel<<<MROWS / 16, 256>>>(W_off2, b_off2);

    // 3) fused: Qeff + Z GEMM + deform-combine + online softmax + @V
    fused_flash_kernel<<<dim3(SQ / 64, BB * NH), 256>>>();

    // 4) output projection + bias
    gemm64_kernel<<<dim3(MROWS / 64, EM / 64), 256>>>(nullptr, W_out, b_out, out, EM, 4);
}

// round 17
// speedup vs baseline: 1.5920x; 1.2723x over previous
#include <cuda_runtime.h>
#include <math.h>
#include <stdint.h>
#include <stddef.h>

#define BB 4
#define SQ 1024
#define EM 256
#define NH 8
#define HD 32
#define MROWS (BB*SQ)          // 4096
#define HID 128                // MLP hidden

#define J2 128                 // column chunk
#define KSTR2 148              // Zs / K-window row stride (floats)
#define QSTR 68                // Qe row stride
#define NCW2 145               // window capacity (spread <= 16 fast path)

// ---------------- scratch (static device globals; allocation-free) ----------
__device__ float g_q[BB*NH*SQ*HD];                 // (b,h,s,d) 4 MB
__device__ float g_k[BB*NH*SQ*HD];
__device__ float g_v[BB*NH*SQ*HD];
__device__ float g_hidden[MROWS*HID];              // 2 MB
__device__ float g_off[MROWS*NH*2];                // (b*S+s)*16 + h*2 + {x,y}
__device__ float g_att[MROWS*EM];                  // (b,s, h*32+d) 4 MB

// ---------------- QKV: one launch, z picks projection ------------------------
__global__ __launch_bounds__(256) void qkv_kernel(const float* __restrict__ A,
                                                  const float* __restrict__ Wq,
                                                  const float* __restrict__ Wk,
                                                  const float* __restrict__ Wv) {
    __shared__ float As[16][68];   // [k][m], padded
    __shared__ float Bs[16][64];   // [k][n]
    const float* W = (blockIdx.z == 0) ? Wq : (blockIdx.z == 1) ? Wk : Wv;
    float* scat    = (blockIdx.z == 0) ? g_q : (blockIdx.z == 1) ? g_k : g_v;
    int tm = blockIdx.x * 64;
    int tn = blockIdx.y * 64;
    int tid = threadIdx.x;
    int tx = tid & 15, ty = tid >> 4;
    float acc[4][4] = {};
    for (int k0 = 0; k0 < EM; k0 += 16) {
        int m  = tid >> 2;
        int kb = (tid & 3) * 4;
        float4 av = *(const float4*)&A[(size_t)(tm + m) * EM + k0 + kb];
        As[kb + 0][m] = av.x; As[kb + 1][m] = av.y;
        As[kb + 2][m] = av.z; As[kb + 3][m] = av.w;
        int kk = tid >> 4;
        int nb = (tid & 15) * 4;
        *(float4*)&Bs[kk][nb] = *(const float4*)&W[(size_t)(k0 + kk) * EM + tn + nb];
        __syncthreads();
#pragma unroll
        for (int k = 0; k < 16; k++) {
            float4 a  = *(const float4*)&As[k][ty * 4];
            float4 bv = *(const float4*)&Bs[k][tx * 4];
            float ar[4] = {a.x, a.y, a.z, a.w};
            float br[4] = {bv.x, bv.y, bv.z, bv.w};
#pragma unroll
            for (int i = 0; i < 4; i++)
#pragma unroll
                for (int j = 0; j < 4; j++) acc[i][j] += ar[i] * br[j];
        }
        __syncthreads();
    }
#pragma unroll
    for (int i = 0; i < 4; i++) {
#pragma unroll
        for (int j = 0; j < 4; j++) {
            int m = tm + ty * 4 + i;
            int n = tn + tx * 4 + j;
            int b = m >> 10, s = m & 1023, h = n >> 5, d = n & 31;
            scat[(((size_t)(b * NH + h)) * SQ + s) * HD + d] = acc[i][j];
        }
    }
}

// ---------------- generic 64x64 GEMM (hidden-GELU / out-proj) ----------------
__global__ __launch_bounds__(256) void gemm64_kernel(const float* __restrict__ A,
                              const float* __restrict__ W,
                              const float* __restrict__ bias,
                              float* __restrict__ outp,
                              int N, int mode) {
    __shared__ float As[16][68];
    __shared__ float Bs[16][64];
    const float* Ap = (mode == 4) ? g_att : A;
    int tm = blockIdx.x * 64;
    int tn = blockIdx.y * 64;
    int tid = threadIdx.x;
    int tx = tid & 15, ty = tid >> 4;
    float acc[4][4] = {};
    for (int k0 = 0; k0 < EM; k0 += 16) {
        int m  = tid >> 2;
        int kb = (tid & 3) * 4;
        float4 av = *(const float4*)&Ap[(size_t)(tm + m) * EM + k0 + kb];
        As[kb + 0][m] = av.x; As[kb + 1][m] = av.y;
        As[kb + 2][m] = av.z; As[kb + 3][m] = av.w;
        int kk = tid >> 4;
        int nb = (tid & 15) * 4;
        *(float4*)&Bs[kk][nb] = *(const float4*)&W[(size_t)(k0 + kk) * N + tn + nb];
        __syncthreads();
#pragma unroll
        for (int k = 0; k < 16; k++) {
            float4 a  = *(const float4*)&As[k][ty * 4];
            float4 bv = *(const float4*)&Bs[k][tx * 4];
            float ar[4] = {a.x, a.y, a.z, a.w};
            float br[4] = {bv.x, bv.y, bv.z, bv.w};
#pragma unroll
            for (int i = 0; i < 4; i++)
#pragma unroll
                for (int j = 0; j < 4; j++) acc[i][j] += ar[i] * br[j];
        }
        __syncthreads();
    }
#pragma unroll
    for (int i = 0; i < 4; i++) {
#pragma unroll
        for (int j = 0; j < 4; j++) {
            int m = tm + ty * 4 + i;
            int n = tn + tx * 4 + j;
            float v = acc[i][j] + bias[n];
            if (mode == 3) {
                v = 0.5f * v * (1.0f + erff(v * 0.70710678118654752f));
                g_hidden[(size_t)m * HID + n] = v;
            } else {
                outp[(size_t)m * EM + n] = v;
            }
        }
    }
}

// ---------------- offset MLP layer 2: (4096,128)@(128,16)+b ------------------
__global__ void off2_kernel(const float* __restrict__ W2,
                            const float* __restrict__ b2) {
    int tid = threadIdx.x;
    int o = tid & 15;
    int r = tid >> 4;
    int row = blockIdx.x * 16 + r;
    float acc = b2[o];
    const float* hrow = &g_hidden[(size_t)row * HID];
#pragma unroll 8
    for (int k = 0; k < HID; k++) acc += hrow[k] * W2[k * 16 + o];
    g_off[(size_t)row * 16 + o] = acc;
}

// ---- guarded global fallback dot (only if offset spread > 16; never in practice)
__device__ __forceinline__ float gdot(const float* __restrict__ Kb, int x, int r,
                                      const float* __restrict__ Qe) {
    if (x < 0 || x >= SQ) return 0.0f;
    float s = 0.0f;
#pragma unroll 8
    for (int k = 0; k < 32; k++) s += Qe[k * QSTR + r] * Kb[(size_t)x * HD + k];
    return s;
}

// ------ fused flash v2: J=128 chunks, 8x4 Z-GEMM, 4r4d PV with j-split -------
__global__ __launch_bounds__(256, 2) void fused_flash2_kernel() {
    extern __shared__ float dsm[];
    float* Zs = dsm;                       // 64*KSTR2 floats (Z tile -> probs)
    float* KV = dsm + 64 * KSTR2;          // 32*KSTR2 (K window) / V chunk 128*32
    float* Qe = KV + 32 * KSTR2;           // 32*QSTR (Qeff, k-major)
    __shared__ float row_wx[64], row_w0[64], row_w1[64];
    __shared__ int   row_ci[64], row_y0[64];
    __shared__ float m_s[64], s_s[64], f_s[64];
    __shared__ float red[64][4];
    __shared__ int s_cmin, s_cmax;

    int bh = blockIdx.y;
    int b = bh >> 3, h = bh & 7;
    int i0 = blockIdx.x * 64;
    int tid = threadIdx.x;

    if (tid == 0) { s_cmin = 0x7fffffff; s_cmax = -0x7fffffff; }
    __syncthreads();

    if (tid < 64) {
        int i = i0 + tid;
        float ox = g_off[((size_t)(b * SQ + i)) * 16 + h * 2 + 0];
        float oy = g_off[((size_t)(b * SQ + i)) * 16 + h * 2 + 1];
        float cxf = floorf(ox); float wx = ox - cxf; int ci = (int)cxf;
        float cyf = floorf(oy); float wy = oy - cyf;
        int y0 = i + (int)cyf;
        bool vy0 = (y0 >= 0) && (y0 <= SQ - 1);
        bool vy1 = (y0 >= -1) && (y0 <= SQ - 2);
        const float scale = 0.17677669529663687f;   // 1/sqrt(32)
        row_wx[tid] = wx;
        row_ci[tid] = ci;
        row_y0[tid] = y0;
        row_w0[tid] = vy0 ? scale * (1.0f - wy) : 0.0f;
        row_w1[tid] = vy1 ? scale * wy : 0.0f;
        m_s[tid] = -3.4e38f;
        s_s[tid] = 0.0f;
        atomicMin(&s_cmin, ci);
        atomicMax(&s_cmax, ci);
    }
    __syncthreads();

    // build Qeff k-major: 4 threads per row, 8 k's each
    {
        int r  = tid >> 2;
        int kq = (tid & 3) * 8;
        int y0 = row_y0[r];
        float w0 = row_w0[r], w1 = row_w1[r];
        const float* Qb = g_q + (size_t)bh * SQ * HD;
        float q0[8] = {0,0,0,0,0,0,0,0}, q1[8] = {0,0,0,0,0,0,0,0};
        if (w0 != 0.0f && y0 >= 0 && y0 < SQ) {
            float4 a = *(const float4*)&Qb[(size_t)y0 * HD + kq];
            float4 c = *(const float4*)&Qb[(size_t)y0 * HD + kq + 4];
            q0[0]=a.x; q0[1]=a.y; q0[2]=a.z; q0[3]=a.w;
            q0[4]=c.x; q0[5]=c.y; q0[6]=c.z; q0[7]=c.w;
        }
        if (w1 != 0.0f && (y0 + 1) >= 0 && (y0 + 1) < SQ) {
            float4 a = *(const float4*)&Qb[(size_t)(y0 + 1) * HD + kq];
            float4 c = *(const float4*)&Qb[(size_t)(y0 + 1) * HD + kq + 4];
            q1[0]=a.x; q1[1]=a.y; q1[2]=a.z; q1[3]=a.w;
            q1[4]=c.x; q1[5]=c.y; q1[6]=c.z; q1[7]=c.w;
        }
#pragma unroll
        for (int t = 0; t < 8; t++)
            Qe[(kq + t) * QSTR + r] = w0 * q0[t] + w1 * q1[t];
    }
    __syncthreads();

    int cmin = s_cmin;
    int ncols = (s_cmax - cmin) + J2 + 1;        // needed Z columns per chunk
    int ncw = ncols < NCW2 ? ncols : NCW2;       // smem-covered columns

    const float* Kb = g_k + (size_t)bh * SQ * HD;
    const float* Vb = g_v + (size_t)bh * SQ * HD;

    // thread maps
    int wq  = tid >> 5;         // Z GEMM: warp id -> 8-row group (Qe broadcast)
    int cg  = tid & 31;         // Z GEMM: 4-col group
    int jj  = tid & 127;        // logits: column
    int rbase = (tid >> 7) * 32;  // logits: 32-row half
    int half = tid >> 7;        // PV: j-half
    int tt   = tid & 127;
    int rg   = tt >> 3;         // PV rows: rg + 16*i (i=0..3)
    int dg   = tt & 7;          // PV cols: dg*4..+4
    float acc[4][4] = {};

    for (int j0 = 0; j0 < SQ; j0 += J2) {
        int xlo = j0 + cmin;
        __syncthreads();   // prev chunk fully consumed

        // A: K window -> KV (k-major), zero-padded outside [0,1023]
        for (int idx = tid; idx < ncw * 8; idx += 256) {
            int col = idx >> 3;
            int kq  = (idx & 7) * 4;
            int x = xlo + col;
            float4 kv4 = make_float4(0.f, 0.f, 0.f, 0.f);
            if (x >= 0 && x < SQ) kv4 = *(const float4*)&Kb[(size_t)x * HD + kq];
            KV[(kq + 0) * KSTR2 + col] = kv4.x;
            KV[(kq + 1) * KSTR2 + col] = kv4.y;
            KV[(kq + 2) * KSTR2 + col] = kv4.z;
            KV[(kq + 3) * KSTR2 + col] = kv4.w;
        }
        __syncthreads();

        // B: Z tile cols 0..127: Qeff(64x32) @ Kwin(32x128), 8x4 per thread
        {
            float za[8][4] = {};
#pragma unroll
            for (int k = 0; k < 32; k++) {
                float4 a0 = *(const float4*)&Qe[k * QSTR + wq * 8];
                float4 a1 = *(const float4*)&Qe[k * QSTR + wq * 8 + 4];
                float4 bv = *(const float4*)&KV[k * KSTR2 + cg * 4];
                float ar[8] = {a0.x, a0.y, a0.z, a0.w, a1.x, a1.y, a1.z, a1.w};
                float br[4] = {bv.x, bv.y, bv.z, bv.w};
#pragma unroll
                for (int i = 0; i < 8; i++)
#pragma unroll
                    for (int j = 0; j < 4; j++) za[i][j] += ar[i] * br[j];
            }
#pragma unroll
            for (int i = 0; i < 8; i++) {
                float4 o; o.x = za[i][0]; o.y = za[i][1]; o.z = za[i][2]; o.w = za[i][3];
                *(float4*)&Zs[(wq * 8 + i) * KSTR2 + cg * 4] = o;
            }
        }
        // C: extra columns 128..ncw-1 (per-dot; tiny count in practice)
        {
            int cnt = ncw - J2;
            for (int idx = tid; idx < 64 * cnt; idx += 256) {
                int r = idx & 63;
                int col = J2 + (idx >> 6);
                float s = 0.0f;
#pragma unroll 8
                for (int k = 0; k < 32; k++) s += Qe[k * QSTR + r] * KV[k * KSTR2 + col];
                Zs[r * KSTR2 + col] = s;
            }
        }
        __syncthreads();

        // D1: 32 logits/thread into regs (reads Zs); V chunk load -> KV
        float L[32];
#pragma unroll
        for (int q = 0; q < 32; q++) {
            int r = rbase + q;
            int zc = jj + row_ci[r] - cmin;
            float z0, z1;
            if (zc + 1 <= ncw - 1) {
                z0 = Zs[r * KSTR2 + zc];
                z1 = Zs[r * KSTR2 + zc + 1];
            } else {
                z0 = (zc <= ncw - 1) ? Zs[r * KSTR2 + zc] : gdot(Kb, xlo + zc, r, Qe);
                z1 = gdot(Kb, xlo + zc + 1, r, Qe);
            }
            float wx = row_wx[r];
            L[q] = (1.0f - wx) * z0 + wx * z1;
        }
#pragma unroll
        for (int s4 = 0; s4 < 4; s4++) {
            int slot = tid + s4 * 256;     // 1024 float4 slots = 128x32 V
            int j = slot >> 3;
            int c = (slot & 7) * 4;
            *(float4*)&KV[j * 32 + c] = *(const float4*)&Vb[(size_t)(j0 + j) * HD + c];
        }
        __syncthreads();   // all Zs reads complete

        // D2: logits -> Zs (now acting as prob buffer)
#pragma unroll
        for (int q = 0; q < 32; q++) Zs[(rbase + q) * KSTR2 + jj] = L[q];
        __syncthreads();

        // chunk max per row (stride-4 interleave: conflict-free)
        {
            int r = tid >> 2, sg = tid & 3;
            float mx = -3.4e38f;
#pragma unroll
            for (int t = 0; t < 32; t++) mx = fmaxf(mx, Zs[r * KSTR2 + sg + 4 * t]);
            red[r][sg] = mx;
        }
        __syncthreads();
        if (tid < 64) {
            float cm = fmaxf(fmaxf(red[tid][0], red[tid][1]),
                             fmaxf(red[tid][2], red[tid][3]));
            float m_old = m_s[tid];
            float m_new = fmaxf(m_old, cm);
            float f = __expf(m_old - m_new);
            f_s[tid] = f;
            s_s[tid] *= f;
            m_s[tid] = m_new;
        }
        __syncthreads();
        // exponentiate in place + partial sums
        {
            int r = tid >> 2, sg = tid & 3;
            float m = m_s[r];
            float sum = 0.0f;
#pragma unroll
            for (int t = 0; t < 32; t++) {
                int ix = r * KSTR2 + sg + 4 * t;
                float p = __expf(Zs[ix] - m);
                Zs[ix] = p;
                sum += p;
            }
            red[r][sg] = sum;
        }
        __syncthreads();
        if (tid < 64)
            s_s[tid] += red[tid][0] + red[tid][1] + red[tid][2] + red[tid][3];
        // PV accumulate: rows rg+16*i, cols dg*4..+4, j-half per thread half
        {
            float fr[4];
#pragma unroll
            for (int i = 0; i < 4; i++) {
                fr[i] = f_s[rg + 16 * i];
#pragma unroll
                for (int c = 0; c < 4; c++) acc[i][c] *= fr[i];
            }
            int jlo = half * 64;
#pragma unroll 4
            for (int j = jlo; j < jlo + 64; j++) {
                float4 v = *(const float4*)&KV[j * 32 + dg * 4];
                float p0 = Zs[(rg +  0) * KSTR2 + j];
                float p1 = Zs[(rg + 16) * KSTR2 + j];
                float p2 = Zs[(rg + 32) * KSTR2 + j];
                float p3 = Zs[(rg + 48) * KSTR2 + j];
                acc[0][0] += p0 * v.x; acc[0][1] += p0 * v.y;
                acc[0][2] += p0 * v.z; acc[0][3] += p0 * v.w;
                acc[1][0] += p1 * v.x; acc[1][1] += p1 * v.y;
                acc[1][2] += p1 * v.z; acc[1][3] += p1 * v.w;
                acc[2][0] += p2 * v.x; acc[2][1] += p2 * v.y;
                acc[2][2] += p2 * v.z; acc[2][3] += p2 * v.w;
                acc[3][0] += p3 * v.x; acc[3][1] += p3 * v.y;
                acc[3][2] += p3 * v.z; acc[3][3] += p3 * v.w;
            }
        }
    }
    // merge the two j-halves (Zs is free now) and write out
    __syncthreads();
    if (half == 1) {
#pragma unroll
        for (int i = 0; i < 4; i++)
            *(float4*)&Zs[tt * 16 + i * 4] = *(float4*)&acc[i][0];
    }
    __syncthreads();
    if (half == 0) {
#pragma unroll
        for (int i = 0; i < 4; i++) {
            int row = rg + 16 * i;
            float inv = 1.0f / s_s[row];
            float4 o2 = *(float4*)&Zs[tt * 16 + i * 4];
            float4 o;
            o.x = (acc[i][0] + o2.x) * inv;
            o.y = (acc[i][1] + o2.y) * inv;
            o.z = (acc[i][2] + o2.z) * inv;
            o.w = (acc[i][3] + o2.w) * inv;
            *(float4*)&g_att[((size_t)(b * SQ + i0 + row)) * EM + h * HD + dg * 4] = o;
        }
    }
}

// ----------------------------- launcher --------------------------------------
extern "C" void kernel_launch(void* const* d_in, const int* in_sizes, int n_in,
                              void* d_out, int out_size) {
    const float* x      = (const float*)d_in[0];
    const float* Wq     = (const float*)d_in[1];
    const float* Wk     = (const float*)d_in[2];
    const float* Wv     = (const float*)d_in[3];
    const float* W_off1 = (const float*)d_in[4];
    const float* b_off1 = (const float*)d_in[5];
    const float* W_off2 = (const float*)d_in[6];
    const float* b_off2 = (const float*)d_in[7];
    const float* W_out  = (const float*)d_in[8];
    const float* b_out  = (const float*)d_in[9];
    float* out = (float*)d_out;

    const int dyn_smem = (64 * KSTR2 + 32 * KSTR2 + 32 * QSTR) * 4;  // 65536 B
    cudaFuncSetAttribute(fused_flash2_kernel,
                         cudaFuncAttributeMaxDynamicSharedMemorySize, dyn_smem);

    // 1) QKV projections — single launch, z selects projection
    qkv_kernel<<<dim3(MROWS / 64, EM / 64, 3), 256>>>(x, Wq, Wk, Wv);

    // 2) offset MLP
    gemm64_kernel<<<dim3(MROWS / 64, HID / 64), 256>>>(x, W_off1, b_off1, nullptr, HID, 3);
    off2_kernel<<<MROWS / 16, 256>>>(W_off2, b_off2);

    // 3) fused: Qeff + Z GEMM + deform-combine + online softmax + @V
    fused_flash2_kernel<<<dim3(SQ / 64, BB * NH), 256, dyn_smem>>>();

    // 4) output projection + bias
    gemm64_kernel<<<dim3(MROWS / 64, EM / 64), 256>>>(nullptr, W_out, b_out, out, EM, 4);
}